// round 4
// baseline (speedup 1.0000x reference)
#include <cuda_runtime.h>
#include <math.h>

#define TOKENS_M 16384   // B*N
#define CTX_M    4096    // B*M
#define EMB      1024
#define CTXD     768
#define NHEAD    16
#define HDIM     64
#define SEQ_N    4096
#define SEQ_M    1024
// softmax computed in exp2 domain: scale = HEAD_DIM^-0.5 * log2(e)
#define SCALE_L2E 0.1803368801111244f

// Scratch (static device globals)
__device__ float g_Q[TOKENS_M * EMB];
__device__ float g_K[CTX_M * EMB];
__device__ float g_V[CTX_M * EMB];
__device__ float g_A[TOKENS_M * EMB];

__device__ __forceinline__ unsigned f2tf(float x) {
    unsigned r;
    asm("cvt.rna.tf32.f32 %0, %1;" : "=r"(r) : "f"(x));
    return r;
}
__device__ __forceinline__ float ex2f(float x) {
    float y;
    asm("ex2.approx.ftz.f32 %0, %1;" : "=f"(y) : "f"(x));
    return y;
}
__device__ __forceinline__ void mma_tf32(
    float& c0, float& c1, float& c2, float& c3,
    unsigned a0, unsigned a1, unsigned a2, unsigned a3,
    unsigned b0, unsigned b1)
{
    asm volatile(
        "mma.sync.aligned.m16n8k8.row.col.f32.tf32.tf32.f32 "
        "{%0,%1,%2,%3}, {%4,%5,%6,%7}, {%8,%9}, {%0,%1,%2,%3};"
        : "+f"(c0), "+f"(c1), "+f"(c2), "+f"(c3)
        : "r"(a0), "r"(a1), "r"(a2), "r"(a3), "r"(b0), "r"(b1));
}

// ---------------------------------------------------------------------------
// TF32 GEMM: C[M,N] = A[M,K] @ B[K,N] (+bias). BM=256, BN=128, BK=16,
// 256 threads = 8 warps (4m x 2n), warp tile 64x64 (mt=4, nt=8).
// Double-buffered smem. Requires M%256==0, N%128==0, K%16==0.
// ---------------------------------------------------------------------------
#define GA_STR 20
#define GB_STR 136
#define GEMM_SMEM ((2 * 256 * GA_STR + 2 * 16 * GB_STR) * 4)

__global__ __launch_bounds__(256) void gemm_tf32(
    const float* __restrict__ A, const float* __restrict__ B,
    float* __restrict__ C, int M, int N, int K, const float* __restrict__ bias)
{
    extern __shared__ unsigned gsm[];
    unsigned* Asm = gsm;                        // [2][256*GA_STR]
    unsigned* Bsm = gsm + 2 * 256 * GA_STR;     // [2][16*GB_STR]

    const int tid  = threadIdx.x;
    const int lane = tid & 31;
    const int wid  = tid >> 5;
    const int wm   = (wid >> 1) * 64;
    const int wn   = (wid & 1) * 64;
    const int bx   = blockIdx.x * 128;
    const int by   = blockIdx.y * 256;

    float acc[4][8][4];
#pragma unroll
    for (int mt = 0; mt < 4; mt++)
#pragma unroll
        for (int nt = 0; nt < 8; nt++)
#pragma unroll
            for (int c = 0; c < 4; c++) acc[mt][nt][c] = 0.f;

    const int nk = K >> 4;

    // stage loader
    auto ld = [&](int st, int k0) {
        unsigned* as = Asm + st * 256 * GA_STR;
        unsigned* bs = Bsm + st * 16 * GB_STR;
#pragma unroll
        for (int i = 0; i < 4; i++) {
            const int idx = tid + 256 * i;
            const int r = idx >> 2, c4 = (idx & 3) << 2;
            float4 v = *(const float4*)(A + (size_t)(by + r) * K + k0 + c4);
            uint4 t;
            t.x = f2tf(v.x); t.y = f2tf(v.y); t.z = f2tf(v.z); t.w = f2tf(v.w);
            *(uint4*)&as[r * GA_STR + c4] = t;
        }
#pragma unroll
        for (int i = 0; i < 2; i++) {
            const int idx = tid + 256 * i;
            const int r = idx >> 5, c = (idx & 31) << 2;
            float4 v = *(const float4*)(B + (size_t)(k0 + r) * N + bx + c);
            uint4 t;
            t.x = f2tf(v.x); t.y = f2tf(v.y); t.z = f2tf(v.z); t.w = f2tf(v.w);
            *(uint4*)&bs[r * GB_STR + c] = t;
        }
    };

    ld(0, 0);
    __syncthreads();

    for (int it = 0; it < nk; it++) {
        const int st = it & 1;
        if (it + 1 < nk) ld(st ^ 1, (it + 1) << 4);

        unsigned* as = Asm + st * 256 * GA_STR;
        unsigned* bs = Bsm + st * 16 * GB_STR;
#pragma unroll
        for (int ks = 0; ks < 2; ks++) {
            unsigned a[4][4], b[8][2];
#pragma unroll
            for (int mt = 0; mt < 4; mt++) {
                const int r = wm + mt * 16 + (lane >> 2);
                const int c = ks * 8 + (lane & 3);
                a[mt][0] = as[r * GA_STR + c];
                a[mt][1] = as[(r + 8) * GA_STR + c];
                a[mt][2] = as[r * GA_STR + c + 4];
                a[mt][3] = as[(r + 8) * GA_STR + c + 4];
            }
#pragma unroll
            for (int nt = 0; nt < 8; nt++) {
                const int col = wn + nt * 8 + (lane >> 2);
                const int rr  = ks * 8 + (lane & 3);
                b[nt][0] = bs[rr * GB_STR + col];
                b[nt][1] = bs[(rr + 4) * GB_STR + col];
            }
#pragma unroll
            for (int mt = 0; mt < 4; mt++)
#pragma unroll
                for (int nt = 0; nt < 8; nt++)
                    mma_tf32(acc[mt][nt][0], acc[mt][nt][1],
                             acc[mt][nt][2], acc[mt][nt][3],
                             a[mt][0], a[mt][1], a[mt][2], a[mt][3],
                             b[nt][0], b[nt][1]);
        }
        __syncthreads();
    }

#pragma unroll
    for (int mt = 0; mt < 4; mt++) {
        const int r0 = by + wm + mt * 16 + (lane >> 2);
#pragma unroll
        for (int nt = 0; nt < 8; nt++) {
            const int col = bx + wn + nt * 8 + 2 * (lane & 3);
            float bv0 = 0.f, bv1 = 0.f;
            if (bias) { bv0 = bias[col]; bv1 = bias[col + 1]; }
            float2 v0 = { acc[mt][nt][0] + bv0, acc[mt][nt][1] + bv1 };
            float2 v1 = { acc[mt][nt][2] + bv0, acc[mt][nt][3] + bv1 };
            *(float2*)(C + (size_t)r0 * N + col) = v0;
            *(float2*)(C + (size_t)(r0 + 8) * N + col) = v1;
        }
    }
}

// ---------------------------------------------------------------------------
// TF32 flash attention, LDS-lean version.
// grid = (SEQ_N/256, NHEAD, B), 256 threads = 8 warps, warp m-tile 32 (mt=2).
// Q staged once in smem; K/V double-buffered 64-key tiles; P kept in
// registers via shfl fragment transform (no smem round trip).
// ---------------------------------------------------------------------------
#define KSTR 68
#define VSTR 72
#define ATTN_SMEM ((256 * KSTR + 2 * 64 * KSTR + 2 * 64 * VSTR) * 4)

__global__ __launch_bounds__(256) void attn_tc(
    const float* __restrict__ Qg, const float* __restrict__ Kg,
    const float* __restrict__ Vg, float* __restrict__ Og)
{
    extern __shared__ unsigned sm[];
    unsigned* Qs = sm;                         // [256][KSTR]
    unsigned* Ks = Qs + 256 * KSTR;            // [2][64][KSTR]
    unsigned* Vs = Ks + 2 * 64 * KSTR;         // [2][64][VSTR]

    const int tid    = threadIdx.x;
    const int lane   = tid & 31;
    const int wid    = tid >> 5;
    const int qbase  = blockIdx.z * SEQ_N + blockIdx.x * 256;
    const int kvbase = blockIdx.z * SEQ_M;
    const int hcol   = blockIdx.y * HDIM;

    // Stage Q tile (256 x 64) once
#pragma unroll
    for (int i = 0; i < 16; i++) {
        const int idx = tid + 256 * i;
        const int r = idx >> 4, c = (idx & 15) << 2;
        float4 v = *(const float4*)(Qg + (size_t)(qbase + r) * EMB + hcol + c);
        uint4 t;
        t.x = f2tf(v.x); t.y = f2tf(v.y); t.z = f2tf(v.z); t.w = f2tf(v.w);
        *(uint4*)&Qs[r * KSTR + c] = t;
    }

    auto stageKV = [&](int st, int kt) {
        unsigned* ks_ = Ks + st * 64 * KSTR;
        unsigned* vs_ = Vs + st * 64 * VSTR;
#pragma unroll
        for (int i = 0; i < 4; i++) {
            const int idx = tid + 256 * i;
            const int r = idx >> 4, c = (idx & 15) << 2;
            const size_t g = (size_t)(kvbase + kt + r) * EMB + hcol + c;
            float4 kv = *(const float4*)(Kg + g);
            float4 vv = *(const float4*)(Vg + g);
            uint4 tk, tv;
            tk.x = f2tf(kv.x); tk.y = f2tf(kv.y); tk.z = f2tf(kv.z); tk.w = f2tf(kv.w);
            tv.x = f2tf(vv.x); tv.y = f2tf(vv.y); tv.z = f2tf(vv.z); tv.w = f2tf(vv.w);
            *(uint4*)&ks_[r * KSTR + c] = tk;
            *(uint4*)&vs_[r * VSTR + c] = tv;
        }
    };

    stageKV(0, 0);

    float mrun[2][2], lrun[2][2], oacc[2][8][4];
#pragma unroll
    for (int mt = 0; mt < 2; mt++) {
        mrun[mt][0] = -1e30f; mrun[mt][1] = -1e30f;
        lrun[mt][0] = 0.f;    lrun[mt][1] = 0.f;
#pragma unroll
        for (int nt = 0; nt < 8; nt++)
#pragma unroll
            for (int c = 0; c < 4; c++) oacc[mt][nt][c] = 0.f;
    }
    __syncthreads();

    const int sl0 = (lane & ~3) | ((lane & 3) >> 1);
    const int sl1 = sl0 + 2;
    const bool oddl = lane & 1;

    for (int it = 0; it < SEQ_M / 64; it++) {
        const int st = it & 1;
        if (it + 1 < SEQ_M / 64) stageKV(st ^ 1, (it + 1) * 64);
        unsigned* ks_ = Ks + st * 64 * KSTR;
        unsigned* vs_ = Vs + st * 64 * VSTR;

        // S = Q @ K^T
        float sacc[2][8][4];
#pragma unroll
        for (int mt = 0; mt < 2; mt++)
#pragma unroll
            for (int nt = 0; nt < 8; nt++)
#pragma unroll
                for (int c = 0; c < 4; c++) sacc[mt][nt][c] = 0.f;

#pragma unroll
        for (int ksi = 0; ksi < 8; ksi++) {
            unsigned aq[2][4];
#pragma unroll
            for (int mt = 0; mt < 2; mt++) {
                const int r = wid * 32 + mt * 16 + (lane >> 2);
                const int c = ksi * 8 + (lane & 3);
                aq[mt][0] = Qs[r * KSTR + c];
                aq[mt][1] = Qs[(r + 8) * KSTR + c];
                aq[mt][2] = Qs[r * KSTR + c + 4];
                aq[mt][3] = Qs[(r + 8) * KSTR + c + 4];
            }
#pragma unroll
            for (int nt = 0; nt < 8; nt++) {
                const int key = nt * 8 + (lane >> 2);
                const int d   = ksi * 8 + (lane & 3);
                const unsigned b0 = ks_[key * KSTR + d];
                const unsigned b1 = ks_[key * KSTR + d + 4];
#pragma unroll
                for (int mt = 0; mt < 2; mt++)
                    mma_tf32(sacc[mt][nt][0], sacc[mt][nt][1],
                             sacc[mt][nt][2], sacc[mt][nt][3],
                             aq[mt][0], aq[mt][1], aq[mt][2], aq[mt][3], b0, b1);
            }
        }

        // Online softmax (exp2 domain)
        float vm[2][2] = { {-1e30f, -1e30f}, {-1e30f, -1e30f} };
#pragma unroll
        for (int mt = 0; mt < 2; mt++)
#pragma unroll
            for (int nt = 0; nt < 8; nt++) {
#pragma unroll
                for (int c = 0; c < 4; c++) sacc[mt][nt][c] *= SCALE_L2E;
                vm[mt][0] = fmaxf(vm[mt][0], fmaxf(sacc[mt][nt][0], sacc[mt][nt][1]));
                vm[mt][1] = fmaxf(vm[mt][1], fmaxf(sacc[mt][nt][2], sacc[mt][nt][3]));
            }
#pragma unroll
        for (int mt = 0; mt < 2; mt++)
#pragma unroll
            for (int h = 0; h < 2; h++) {
                float v = vm[mt][h];
                v = fmaxf(v, __shfl_xor_sync(0xffffffffu, v, 1));
                v = fmaxf(v, __shfl_xor_sync(0xffffffffu, v, 2));
                vm[mt][h] = v;
            }

        float corr[2][2], rs[2][2];
#pragma unroll
        for (int mt = 0; mt < 2; mt++)
#pragma unroll
            for (int h = 0; h < 2; h++) {
                const float mn = fmaxf(mrun[mt][h], vm[mt][h]);
                corr[mt][h] = ex2f(mrun[mt][h] - mn);
                mrun[mt][h] = mn;
                rs[mt][h] = 0.f;
            }
#pragma unroll
        for (int mt = 0; mt < 2; mt++)
#pragma unroll
            for (int nt = 0; nt < 8; nt++) {
                sacc[mt][nt][0] = ex2f(sacc[mt][nt][0] - mrun[mt][0]);
                sacc[mt][nt][1] = ex2f(sacc[mt][nt][1] - mrun[mt][0]);
                sacc[mt][nt][2] = ex2f(sacc[mt][nt][2] - mrun[mt][1]);
                sacc[mt][nt][3] = ex2f(sacc[mt][nt][3] - mrun[mt][1]);
                rs[mt][0] += sacc[mt][nt][0] + sacc[mt][nt][1];
                rs[mt][1] += sacc[mt][nt][2] + sacc[mt][nt][3];
            }
#pragma unroll
        for (int mt = 0; mt < 2; mt++)
#pragma unroll
            for (int h = 0; h < 2; h++) {
                float r = rs[mt][h];
                r += __shfl_xor_sync(0xffffffffu, r, 1);
                r += __shfl_xor_sync(0xffffffffu, r, 2);
                lrun[mt][h] = lrun[mt][h] * corr[mt][h] + r;
            }
#pragma unroll
        for (int mt = 0; mt < 2; mt++)
#pragma unroll
            for (int nt = 0; nt < 8; nt++) {
                oacc[mt][nt][0] *= corr[mt][0]; oacc[mt][nt][1] *= corr[mt][0];
                oacc[mt][nt][2] *= corr[mt][1]; oacc[mt][nt][3] *= corr[mt][1];
            }

        // O += P @ V, with P fragments produced in-register via shfl
#pragma unroll
        for (int ksi = 0; ksi < 8; ksi++) {
            unsigned pa[2][4];
#pragma unroll
            for (int mt = 0; mt < 2; mt++) {
                const float c0 = sacc[mt][ksi][0], c1 = sacc[mt][ksi][1];
                const float c2 = sacc[mt][ksi][2], c3 = sacc[mt][ksi][3];
                const float e00 = __shfl_sync(0xffffffffu, c0, sl0);
                const float e01 = __shfl_sync(0xffffffffu, c1, sl0);
                const float e20 = __shfl_sync(0xffffffffu, c2, sl0);
                const float e21 = __shfl_sync(0xffffffffu, c3, sl0);
                const float f00 = __shfl_sync(0xffffffffu, c0, sl1);
                const float f01 = __shfl_sync(0xffffffffu, c1, sl1);
                const float f20 = __shfl_sync(0xffffffffu, c2, sl1);
                const float f21 = __shfl_sync(0xffffffffu, c3, sl1);
                pa[mt][0] = f2tf(oddl ? e01 : e00);
                pa[mt][1] = f2tf(oddl ? e21 : e20);
                pa[mt][2] = f2tf(oddl ? f01 : f00);
                pa[mt][3] = f2tf(oddl ? f21 : f20);
            }
#pragma unroll
            for (int nt = 0; nt < 8; nt++) {
                const int key = ksi * 8 + (lane & 3);
                const int dv  = nt * 8 + (lane >> 2);
                const unsigned b0 = vs_[key * VSTR + dv];
                const unsigned b1 = vs_[(key + 4) * VSTR + dv];
#pragma unroll
                for (int mt = 0; mt < 2; mt++)
                    mma_tf32(oacc[mt][nt][0], oacc[mt][nt][1],
                             oacc[mt][nt][2], oacc[mt][nt][3],
                             pa[mt][0], pa[mt][1], pa[mt][2], pa[mt][3], b0, b1);
            }
        }
        __syncthreads();
    }

    // Epilogue
#pragma unroll
    for (int mt = 0; mt < 2; mt++) {
        const float inv0 = 1.f / lrun[mt][0];
        const float inv1 = 1.f / lrun[mt][1];
        const int r0 = qbase + wid * 32 + mt * 16 + (lane >> 2);
#pragma unroll
        for (int nt = 0; nt < 8; nt++) {
            const int col = hcol + nt * 8 + 2 * (lane & 3);
            float2 v0 = { oacc[mt][nt][0] * inv0, oacc[mt][nt][1] * inv0 };
            float2 v1 = { oacc[mt][nt][2] * inv1, oacc[mt][nt][3] * inv1 };
            *(float2*)(Og + (size_t)r0 * EMB + col) = v0;
            *(float2*)(Og + (size_t)(r0 + 8) * EMB + col) = v1;
        }
    }
}

// ---------------------------------------------------------------------------
extern "C" void kernel_launch(void* const* d_in, const int* in_sizes, int n_in,
                              void* d_out, int out_size)
{
    const float* tokens  = (const float*)d_in[0];
    const float* context = (const float*)d_in[1];
    const float* Wq      = (const float*)d_in[2];
    const float* Wk      = (const float*)d_in[3];
    const float* Wv      = (const float*)d_in[4];
    const float* Wo      = (const float*)d_in[5];
    const float* bo      = (const float*)d_in[6];
    float* out = (float*)d_out;

    float *gQ, *gK, *gV, *gA;
    cudaGetSymbolAddress((void**)&gQ, g_Q);
    cudaGetSymbolAddress((void**)&gK, g_K);
    cudaGetSymbolAddress((void**)&gV, g_V);
    cudaGetSymbolAddress((void**)&gA, g_A);

    cudaFuncSetAttribute(gemm_tf32,
                         cudaFuncAttributeMaxDynamicSharedMemorySize, GEMM_SMEM);
    cudaFuncSetAttribute(attn_tc,
                         cudaFuncAttributeMaxDynamicSharedMemorySize, ATTN_SMEM);

    // Projections
    gemm_tf32<<<dim3(EMB / 128, TOKENS_M / 256), 256, GEMM_SMEM>>>(
        tokens, Wq, gQ, TOKENS_M, EMB, EMB, nullptr);
    gemm_tf32<<<dim3(EMB / 128, CTX_M / 256), 256, GEMM_SMEM>>>(
        context, Wk, gK, CTX_M, EMB, CTXD, nullptr);
    gemm_tf32<<<dim3(EMB / 128, CTX_M / 256), 256, GEMM_SMEM>>>(
        context, Wv, gV, CTX_M, EMB, CTXD, nullptr);

    // Fused attention
    attn_tc<<<dim3(SEQ_N / 256, NHEAD, 4), 256, ATTN_SMEM>>>(gQ, gK, gV, gA);

    // Output projection + bias
    gemm_tf32<<<dim3(EMB / 128, TOKENS_M / 256), 256, GEMM_SMEM>>>(
        gA, Wo, out, TOKENS_M, EMB, EMB, bo);
}

// round 5
// speedup vs baseline: 1.4065x; 1.4065x over previous
#include <cuda_runtime.h>
#include <cuda_fp16.h>
#include <math.h>

#define TOKENS_M 16384   // B*N
#define CTX_M    4096    // B*M
#define EMB      1024
#define CTXD     768
#define NHEAD    16
#define HDIM     64
#define SEQ_N    4096
#define SEQ_M    1024
// softmax in exp2 domain: HEAD_DIM^-0.5 * log2(e)
#define SCALE_L2E 0.1803368801111244f

// Scratch (static device globals)
__device__ float g_Q[TOKENS_M * EMB];
__device__ float g_K[CTX_M * EMB];
__device__ float g_V[CTX_M * EMB];
__device__ float g_A[TOKENS_M * EMB];

__device__ __forceinline__ float ex2f(float x) {
    float y;
    asm("ex2.approx.ftz.f32 %0, %1;" : "=f"(y) : "f"(x));
    return y;
}
__device__ __forceinline__ unsigned packh2(float lo, float hi) {
    __half2 h = __floats2half2_rn(lo, hi);
    return *reinterpret_cast<unsigned*>(&h);
}
__device__ __forceinline__ void mma_f16(
    float& c0, float& c1, float& c2, float& c3,
    unsigned a0, unsigned a1, unsigned a2, unsigned a3,
    unsigned b0, unsigned b1)
{
    asm volatile(
        "mma.sync.aligned.m16n8k16.row.col.f32.f16.f16.f32 "
        "{%0,%1,%2,%3}, {%4,%5,%6,%7}, {%8,%9}, {%0,%1,%2,%3};"
        : "+f"(c0), "+f"(c1), "+f"(c2), "+f"(c3)
        : "r"(a0), "r"(a1), "r"(a2), "r"(a3), "r"(b0), "r"(b1));
}

// ---------------------------------------------------------------------------
// FP16 tensor-core GEMM: C[M,N] = A[M,K] @ B[K,N] (+bias), fp32 accum.
// BM=BN=128, BK=32, 256 threads, warps 2(m)x4(n), warp tile 64x32 (mt=4,nt=4).
// As stored [row][k] (k-major), Bs stored TRANSPOSED [n][k].
// Requires M%128==0, N%128==0, K%32==0.
// ---------------------------------------------------------------------------
#define ASH 40   // As row stride (halves) = 20 words -> conflict-free frags
#define BSH 40   // Bs row stride (halves)

__global__ __launch_bounds__(256) void gemm_f16(
    const float* __restrict__ A, const float* __restrict__ B,
    float* __restrict__ C, int M, int N, int K, const float* __restrict__ bias)
{
    __shared__ __half As[128 * ASH];
    __shared__ __half Bs[128 * BSH];
    const unsigned* As32 = (const unsigned*)As;
    const unsigned* Bs32 = (const unsigned*)Bs;

    const int tid  = threadIdx.x;
    const int lane = tid & 31;
    const int wid  = tid >> 5;
    const int wm   = (wid >> 2) * 64;
    const int wn   = (wid & 3) * 32;
    const int bx   = blockIdx.x * 128;
    const int by   = blockIdx.y * 128;

    float acc[4][4][4];
#pragma unroll
    for (int mt = 0; mt < 4; mt++)
#pragma unroll
        for (int nt = 0; nt < 4; nt++)
#pragma unroll
            for (int c = 0; c < 4; c++) acc[mt][nt][c] = 0.f;

    for (int k0 = 0; k0 < K; k0 += 32) {
        // Stage A (128x32) k-major: coalesced float4 loads
#pragma unroll
        for (int i = 0; i < 4; i++) {
            const int idx = tid + 256 * i;
            const int r = idx >> 3, c = (idx & 7) * 4;
            float4 v = *(const float4*)(A + (size_t)(by + r) * K + k0 + c);
            uint2 u;
            u.x = packh2(v.x, v.y);
            u.y = packh2(v.z, v.w);
            *(uint2*)&As[r * ASH + c] = u;
        }
        // Stage B (32x128) transposed -> Bs[n][k]; strided gmem load so the
        // transpose stores are merged/conflict-free
#pragma unroll
        for (int i = 0; i < 4; i++) {
            const int idx = tid + 256 * i;
            const int r = idx & 31;            // k (consecutive across lanes)
            const int nb = (idx >> 5) * 4;     // n group of 4
            float4 v = *(const float4*)(B + (size_t)(k0 + r) * N + bx + nb);
            Bs[(nb + 0) * BSH + r] = __float2half_rn(v.x);
            Bs[(nb + 1) * BSH + r] = __float2half_rn(v.y);
            Bs[(nb + 2) * BSH + r] = __float2half_rn(v.z);
            Bs[(nb + 3) * BSH + r] = __float2half_rn(v.w);
        }
        __syncthreads();

#pragma unroll
        for (int ks = 0; ks < 2; ks++) {       // two k16 steps per BK=32
            unsigned a[4][4], b[4][2];
#pragma unroll
            for (int mt = 0; mt < 4; mt++) {
                const int r = wm + mt * 16 + (lane >> 2);
                const int w = ks * 8 + (lane & 3);          // word offset in row
                a[mt][0] = As32[r * 20 + w];
                a[mt][1] = As32[(r + 8) * 20 + w];
                a[mt][2] = As32[r * 20 + w + 4];
                a[mt][3] = As32[(r + 8) * 20 + w + 4];
            }
#pragma unroll
            for (int nt = 0; nt < 4; nt++) {
                const int n = wn + nt * 8 + (lane >> 2);
                const int w = ks * 8 + (lane & 3);
                b[nt][0] = Bs32[n * 20 + w];
                b[nt][1] = Bs32[n * 20 + w + 4];
            }
#pragma unroll
            for (int mt = 0; mt < 4; mt++)
#pragma unroll
                for (int nt = 0; nt < 4; nt++)
                    mma_f16(acc[mt][nt][0], acc[mt][nt][1],
                            acc[mt][nt][2], acc[mt][nt][3],
                            a[mt][0], a[mt][1], a[mt][2], a[mt][3],
                            b[nt][0], b[nt][1]);
        }
        __syncthreads();
    }

#pragma unroll
    for (int mt = 0; mt < 4; mt++) {
        const int r0 = by + wm + mt * 16 + (lane >> 2);
#pragma unroll
        for (int nt = 0; nt < 4; nt++) {
            const int col = bx + wn + nt * 8 + 2 * (lane & 3);
            float bv0 = 0.f, bv1 = 0.f;
            if (bias) { bv0 = bias[col]; bv1 = bias[col + 1]; }
            float2 v0 = { acc[mt][nt][0] + bv0, acc[mt][nt][1] + bv1 };
            float2 v1 = { acc[mt][nt][2] + bv0, acc[mt][nt][3] + bv1 };
            *(float2*)(C + (size_t)r0 * N + col) = v0;
            *(float2*)(C + (size_t)(r0 + 8) * N + col) = v1;
        }
    }
}

// ---------------------------------------------------------------------------
// FP16 flash attention. grid=(SEQ_N/256, NHEAD, B), 256 thr = 8 warps,
// warp m-tile 32 (mt=2). Q staged once; K/V double-buffered 64-key tiles;
// V staged transposed [dv][key]; P stays in registers (C-frag == A-frag).
// ---------------------------------------------------------------------------
#define QSH 72   // half stride = 36 words
#define ATTN_SMEM ((256 * QSH + 2 * 64 * QSH + 2 * 64 * QSH) * 2)

__global__ __launch_bounds__(256) void attn_tc(
    const float* __restrict__ Qg, const float* __restrict__ Kg,
    const float* __restrict__ Vg, float* __restrict__ Og)
{
    extern __shared__ __half sm[];
    __half* Qs = sm;                       // [256][QSH]  q x d
    __half* Ks = Qs + 256 * QSH;           // [2][64][QSH] key x d
    __half* Vs = Ks + 2 * 64 * QSH;        // [2][64][QSH] dv x key (transposed)

    const int tid    = threadIdx.x;
    const int lane   = tid & 31;
    const int wid    = tid >> 5;
    const int qbase  = blockIdx.z * SEQ_N + blockIdx.x * 256;
    const int kvbase = blockIdx.z * SEQ_M;
    const int hcol   = blockIdx.y * HDIM;

    // Stage Q (256 x 64) once, k-major, coalesced
#pragma unroll
    for (int i = 0; i < 16; i++) {
        const int idx = tid + 256 * i;
        const int r = idx >> 4, c = (idx & 15) * 4;
        float4 v = *(const float4*)(Qg + (size_t)(qbase + r) * EMB + hcol + c);
        uint2 u;
        u.x = packh2(v.x, v.y);
        u.y = packh2(v.z, v.w);
        *(uint2*)&Qs[r * QSH + c] = u;
    }

    auto stageKV = [&](int st, int kt) {
        __half* ks_ = Ks + st * 64 * QSH;
        __half* vs_ = Vs + st * 64 * QSH;
        // K: coalesced, k-major
#pragma unroll
        for (int i = 0; i < 4; i++) {
            const int idx = tid + 256 * i;
            const int r = idx >> 4, c = (idx & 15) * 4;
            float4 v = *(const float4*)(Kg + (size_t)(kvbase + kt + r) * EMB + hcol + c);
            uint2 u;
            u.x = packh2(v.x, v.y);
            u.y = packh2(v.z, v.w);
            *(uint2*)&ks_[r * QSH + c] = u;
        }
        // V: strided load (lane-consecutive keys) -> merged transpose stores
#pragma unroll
        for (int i = 0; i < 4; i++) {
            const int idx = tid + 256 * i;
            const int r = idx & 63;            // key
            const int c = (idx >> 6) * 4;      // dv group of 4
            float4 v = *(const float4*)(Vg + (size_t)(kvbase + kt + r) * EMB + hcol + c);
            vs_[(c + 0) * QSH + r] = __float2half_rn(v.x);
            vs_[(c + 1) * QSH + r] = __float2half_rn(v.y);
            vs_[(c + 2) * QSH + r] = __float2half_rn(v.z);
            vs_[(c + 3) * QSH + r] = __float2half_rn(v.w);
        }
    };

    stageKV(0, 0);

    float mrun[2][2], lrun[2][2], oacc[2][8][4];
#pragma unroll
    for (int mt = 0; mt < 2; mt++) {
        mrun[mt][0] = -1e30f; mrun[mt][1] = -1e30f;
        lrun[mt][0] = 0.f;    lrun[mt][1] = 0.f;
#pragma unroll
        for (int nt = 0; nt < 8; nt++)
#pragma unroll
            for (int c = 0; c < 4; c++) oacc[mt][nt][c] = 0.f;
    }
    __syncthreads();

    for (int it = 0; it < SEQ_M / 64; it++) {
        const int st = it & 1;
        if (it + 1 < SEQ_M / 64) stageKV(st ^ 1, (it + 1) * 64);
        const unsigned* ks32 = (const unsigned*)(Ks + st * 64 * QSH);
        const unsigned* vs32 = (const unsigned*)(Vs + st * 64 * QSH);
        const unsigned* qs32 = (const unsigned*)Qs;

        // S = Q @ K^T  (4 k16 steps over d=64)
        float sacc[2][8][4];
#pragma unroll
        for (int mt = 0; mt < 2; mt++)
#pragma unroll
            for (int nt = 0; nt < 8; nt++)
#pragma unroll
                for (int c = 0; c < 4; c++) sacc[mt][nt][c] = 0.f;

#pragma unroll
        for (int ksi = 0; ksi < 4; ksi++) {
            unsigned aq[2][4];
#pragma unroll
            for (int mt = 0; mt < 2; mt++) {
                const int r = wid * 32 + mt * 16 + (lane >> 2);
                const int w = ksi * 8 + (lane & 3);
                aq[mt][0] = qs32[r * 36 + w];
                aq[mt][1] = qs32[(r + 8) * 36 + w];
                aq[mt][2] = qs32[r * 36 + w + 4];
                aq[mt][3] = qs32[(r + 8) * 36 + w + 4];
            }
#pragma unroll
            for (int nt = 0; nt < 8; nt++) {
                const int key = nt * 8 + (lane >> 2);
                const int w   = ksi * 8 + (lane & 3);
                const unsigned b0 = ks32[key * 36 + w];
                const unsigned b1 = ks32[key * 36 + w + 4];
#pragma unroll
                for (int mt = 0; mt < 2; mt++)
                    mma_f16(sacc[mt][nt][0], sacc[mt][nt][1],
                            sacc[mt][nt][2], sacc[mt][nt][3],
                            aq[mt][0], aq[mt][1], aq[mt][2], aq[mt][3], b0, b1);
            }
        }

        // Online softmax (exp2 domain), fp32 C-fragments
        float vm[2][2] = { {-1e30f, -1e30f}, {-1e30f, -1e30f} };
#pragma unroll
        for (int mt = 0; mt < 2; mt++)
#pragma unroll
            for (int nt = 0; nt < 8; nt++) {
#pragma unroll
                for (int c = 0; c < 4; c++) sacc[mt][nt][c] *= SCALE_L2E;
                vm[mt][0] = fmaxf(vm[mt][0], fmaxf(sacc[mt][nt][0], sacc[mt][nt][1]));
                vm[mt][1] = fmaxf(vm[mt][1], fmaxf(sacc[mt][nt][2], sacc[mt][nt][3]));
            }
#pragma unroll
        for (int mt = 0; mt < 2; mt++)
#pragma unroll
            for (int h = 0; h < 2; h++) {
                float v = vm[mt][h];
                v = fmaxf(v, __shfl_xor_sync(0xffffffffu, v, 1));
                v = fmaxf(v, __shfl_xor_sync(0xffffffffu, v, 2));
                vm[mt][h] = v;
            }

        float corr[2][2], rs[2][2];
#pragma unroll
        for (int mt = 0; mt < 2; mt++)
#pragma unroll
            for (int h = 0; h < 2; h++) {
                const float mn = fmaxf(mrun[mt][h], vm[mt][h]);
                corr[mt][h] = ex2f(mrun[mt][h] - mn);
                mrun[mt][h] = mn;
                rs[mt][h] = 0.f;
            }
#pragma unroll
        for (int mt = 0; mt < 2; mt++)
#pragma unroll
            for (int nt = 0; nt < 8; nt++) {
                sacc[mt][nt][0] = ex2f(sacc[mt][nt][0] - mrun[mt][0]);
                sacc[mt][nt][1] = ex2f(sacc[mt][nt][1] - mrun[mt][0]);
                sacc[mt][nt][2] = ex2f(sacc[mt][nt][2] - mrun[mt][1]);
                sacc[mt][nt][3] = ex2f(sacc[mt][nt][3] - mrun[mt][1]);
                rs[mt][0] += sacc[mt][nt][0] + sacc[mt][nt][1];
                rs[mt][1] += sacc[mt][nt][2] + sacc[mt][nt][3];
            }
#pragma unroll
        for (int mt = 0; mt < 2; mt++)
#pragma unroll
            for (int h = 0; h < 2; h++) {
                float r = rs[mt][h];
                r += __shfl_xor_sync(0xffffffffu, r, 1);
                r += __shfl_xor_sync(0xffffffffu, r, 2);
                lrun[mt][h] = lrun[mt][h] * corr[mt][h] + r;
            }
#pragma unroll
        for (int mt = 0; mt < 2; mt++)
#pragma unroll
            for (int nt = 0; nt < 8; nt++) {
                oacc[mt][nt][0] *= corr[mt][0]; oacc[mt][nt][1] *= corr[mt][0];
                oacc[mt][nt][2] *= corr[mt][1]; oacc[mt][nt][3] *= corr[mt][1];
            }

        // O += P @ V : P A-fragments come straight from sacc (C-frag == A-frag)
#pragma unroll
        for (int ksi = 0; ksi < 4; ksi++) {
            unsigned pa[2][4];
#pragma unroll
            for (int mt = 0; mt < 2; mt++) {
                pa[mt][0] = packh2(sacc[mt][2 * ksi][0],     sacc[mt][2 * ksi][1]);
                pa[mt][1] = packh2(sacc[mt][2 * ksi][2],     sacc[mt][2 * ksi][3]);
                pa[mt][2] = packh2(sacc[mt][2 * ksi + 1][0], sacc[mt][2 * ksi + 1][1]);
                pa[mt][3] = packh2(sacc[mt][2 * ksi + 1][2], sacc[mt][2 * ksi + 1][3]);
            }
#pragma unroll
            for (int nt = 0; nt < 8; nt++) {
                const int dv = nt * 8 + (lane >> 2);
                const int w  = ksi * 8 + (lane & 3);
                const unsigned b0 = vs32[dv * 36 + w];
                const unsigned b1 = vs32[dv * 36 + w + 4];
#pragma unroll
                for (int mt = 0; mt < 2; mt++)
                    mma_f16(oacc[mt][nt][0], oacc[mt][nt][1],
                            oacc[mt][nt][2], oacc[mt][nt][3],
                            pa[mt][0], pa[mt][1], pa[mt][2], pa[mt][3], b0, b1);
            }
        }
        __syncthreads();
    }

    // Epilogue
#pragma unroll
    for (int mt = 0; mt < 2; mt++) {
        const float inv0 = 1.f / lrun[mt][0];
        const float inv1 = 1.f / lrun[mt][1];
        const int r0 = qbase + wid * 32 + mt * 16 + (lane >> 2);
#pragma unroll
        for (int nt = 0; nt < 8; nt++) {
            const int col = hcol + nt * 8 + 2 * (lane & 3);
            float2 v0 = { oacc[mt][nt][0] * inv0, oacc[mt][nt][1] * inv0 };
            float2 v1 = { oacc[mt][nt][2] * inv1, oacc[mt][nt][3] * inv1 };
            *(float2*)(Og + (size_t)r0 * EMB + col) = v0;
            *(float2*)(Og + (size_t)(r0 + 8) * EMB + col) = v1;
        }
    }
}

// ---------------------------------------------------------------------------
extern "C" void kernel_launch(void* const* d_in, const int* in_sizes, int n_in,
                              void* d_out, int out_size)
{
    const float* tokens  = (const float*)d_in[0];
    const float* context = (const float*)d_in[1];
    const float* Wq      = (const float*)d_in[2];
    const float* Wk      = (const float*)d_in[3];
    const float* Wv      = (const float*)d_in[4];
    const float* Wo      = (const float*)d_in[5];
    const float* bo      = (const float*)d_in[6];
    float* out = (float*)d_out;

    float *gQ, *gK, *gV, *gA;
    cudaGetSymbolAddress((void**)&gQ, g_Q);
    cudaGetSymbolAddress((void**)&gK, g_K);
    cudaGetSymbolAddress((void**)&gV, g_V);
    cudaGetSymbolAddress((void**)&gA, g_A);

    cudaFuncSetAttribute(attn_tc,
                         cudaFuncAttributeMaxDynamicSharedMemorySize, ATTN_SMEM);

    // Projections (fp16 tensor cores, fp32 accumulate)
    gemm_f16<<<dim3(EMB / 128, TOKENS_M / 128), 256>>>(tokens, Wq, gQ,
                                                       TOKENS_M, EMB, EMB, nullptr);
    gemm_f16<<<dim3(EMB / 128, CTX_M / 128), 256>>>(context, Wk, gK,
                                                    CTX_M, EMB, CTXD, nullptr);
    gemm_f16<<<dim3(EMB / 128, CTX_M / 128), 256>>>(context, Wv, gV,
                                                    CTX_M, EMB, CTXD, nullptr);

    // Fused attention
    attn_tc<<<dim3(SEQ_N / 256, NHEAD, 4), 256, ATTN_SMEM>>>(gQ, gK, gV, gA);

    // Output projection + bias
    gemm_f16<<<dim3(EMB / 128, TOKENS_M / 128), 256>>>(gA, Wo, out,
                                                       TOKENS_M, EMB, EMB, bo);
}

// round 6
// speedup vs baseline: 2.5810x; 1.8351x over previous
#include <cuda_runtime.h>
#include <cuda_fp16.h>
#include <math.h>

#define TOKENS_M 16384   // B*N
#define CTX_M    4096    // B*M
#define EMB      1024
#define CTXD     768
#define NHEAD    16
#define HDIM     64
#define SEQ_N    4096
#define SEQ_M    1024
#define SCALE_L2E 0.1803368801111244f   // HEAD_DIM^-0.5 * log2(e)

// fp16 scratch (static device globals)
__device__ __half g_ht[TOKENS_M * EMB];    // tokens fp16
__device__ __half g_hc[CTX_M * CTXD];      // context fp16
__device__ __half g_hwq[EMB * EMB];
__device__ __half g_hwk[CTXD * EMB];
__device__ __half g_hwv[CTXD * EMB];
__device__ __half g_hwo[EMB * EMB];
__device__ __half g_hQ[TOKENS_M * EMB];
__device__ __half g_hK[CTX_M * EMB];
__device__ __half g_hV[CTX_M * EMB];
__device__ __half g_hA[TOKENS_M * EMB];

__device__ __forceinline__ float ex2f(float x) {
    float y;
    asm("ex2.approx.ftz.f32 %0, %1;" : "=f"(y) : "f"(x));
    return y;
}
__device__ __forceinline__ unsigned packh2(float lo, float hi) {
    __half2 h = __floats2half2_rn(lo, hi);
    return *reinterpret_cast<unsigned*>(&h);
}
__device__ __forceinline__ unsigned s2u(const void* p) {
    return (unsigned)__cvta_generic_to_shared(p);
}
__device__ __forceinline__ void cp16(unsigned dst, const void* src) {
    asm volatile("cp.async.cg.shared.global [%0], [%1], 16;" :: "r"(dst), "l"(src));
}
__device__ __forceinline__ void cp_commit() {
    asm volatile("cp.async.commit_group;");
}
template<int N> __device__ __forceinline__ void cp_wait() {
    asm volatile("cp.async.wait_group %0;" :: "n"(N));
}
__device__ __forceinline__ void ldsm4(unsigned* r, unsigned a) {
    asm volatile("ldmatrix.sync.aligned.m8n8.x4.shared.b16 {%0,%1,%2,%3}, [%4];"
        : "=r"(r[0]), "=r"(r[1]), "=r"(r[2]), "=r"(r[3]) : "r"(a));
}
__device__ __forceinline__ void ldsm4t(unsigned* r, unsigned a) {
    asm volatile("ldmatrix.sync.aligned.m8n8.x4.trans.shared.b16 {%0,%1,%2,%3}, [%4];"
        : "=r"(r[0]), "=r"(r[1]), "=r"(r[2]), "=r"(r[3]) : "r"(a));
}
__device__ __forceinline__ void mma_f16(
    float& c0, float& c1, float& c2, float& c3,
    unsigned a0, unsigned a1, unsigned a2, unsigned a3,
    unsigned b0, unsigned b1)
{
    asm volatile(
        "mma.sync.aligned.m16n8k16.row.col.f32.f16.f16.f32 "
        "{%0,%1,%2,%3}, {%4,%5,%6,%7}, {%8,%9}, {%0,%1,%2,%3};"
        : "+f"(c0), "+f"(c1), "+f"(c2), "+f"(c3)
        : "r"(a0), "r"(a1), "r"(a2), "r"(a3), "r"(b0), "r"(b1));
}

// ---------------------------------------------------------------------------
// fp32 -> fp16 convert (vectorized)
// ---------------------------------------------------------------------------
__global__ void f2h(const float4* __restrict__ s, uint2* __restrict__ d, int n4)
{
    int i = blockIdx.x * blockDim.x + threadIdx.x;
    if (i < n4) {
        float4 v = s[i];
        uint2 u;
        u.x = packh2(v.x, v.y);
        u.y = packh2(v.z, v.w);
        d[i] = u;
    }
}

// ---------------------------------------------------------------------------
// fp16 GEMM: C[M,N] = A[M,K] @ B[K,N] (+bias), fp32 accum.
// BM=BN=128, BK=32, 256 thr, warps 2m x 4n, warp tile 64x32.
// A staged [m][k] (stride 40 halves), B staged [k][n] (stride 136 halves);
// fragments via ldmatrix (.trans for B). cp.async double buffered.
// HOUT: write __half C, else float C (+bias).
// ---------------------------------------------------------------------------
#define ASH 40    // halves
#define BSH 136   // halves

template<bool HOUT>
__global__ __launch_bounds__(256) void gemm_h(
    const __half* __restrict__ A, const __half* __restrict__ B,
    void* __restrict__ Cv, int M, int N, int K, const float* __restrict__ bias)
{
    __shared__ __align__(16) __half smem[2 * 128 * ASH + 2 * 32 * BSH];
    __half* Asm[2] = { smem, smem + 128 * ASH };
    __half* Bsm[2] = { smem + 2 * 128 * ASH, smem + 2 * 128 * ASH + 32 * BSH };

    const int tid  = threadIdx.x;
    const int lane = tid & 31;
    const int wid  = tid >> 5;
    const int wm   = (wid >> 2) * 64;
    const int wn   = (wid & 3) * 32;
    const int bx   = blockIdx.x * 128;
    const int by   = blockIdx.y * 128;

    float acc[4][4][4];
#pragma unroll
    for (int mt = 0; mt < 4; mt++)
#pragma unroll
        for (int nt = 0; nt < 4; nt++)
#pragma unroll
            for (int c = 0; c < 4; c++) acc[mt][nt][c] = 0.f;

    auto issue = [&](int st, int k0) {
#pragma unroll
        for (int i = 0; i < 2; i++) {         // A: 128 rows x 4 chunks
            const int idx = tid + 256 * i;
            const int r = idx >> 2, c = idx & 3;
            cp16(s2u(Asm[st] + r * ASH + c * 8),
                 A + (size_t)(by + r) * K + k0 + c * 8);
        }
#pragma unroll
        for (int i = 0; i < 2; i++) {         // B: 32 rows x 16 chunks
            const int idx = tid + 256 * i;
            const int r = idx >> 4, c = idx & 15;
            cp16(s2u(Bsm[st] + r * BSH + c * 8),
                 B + (size_t)(k0 + r) * N + bx + c * 8);
        }
        cp_commit();
    };

    const int nk = K >> 5;
    issue(0, 0);

    for (int it = 0; it < nk; it++) {
        const int st = it & 1;
        if (it + 1 < nk) { issue(st ^ 1, (it + 1) << 5); cp_wait<1>(); }
        else             { cp_wait<0>(); }
        __syncthreads();

        const __half* as = Asm[st];
        const __half* bs = Bsm[st];
        unsigned bfr[4][4];
#pragma unroll
        for (int nt = 0; nt < 4; nt++)
            ldsm4t(bfr[nt], s2u(bs + lane * BSH + wn + nt * 8));
#pragma unroll
        for (int ks = 0; ks < 2; ks++) {
            unsigned afr[4][4];
#pragma unroll
            for (int mt = 0; mt < 4; mt++)
                ldsm4(afr[mt], s2u(as + (wm + mt * 16 + (lane & 15)) * ASH
                                      + ks * 16 + ((lane >> 4) << 3)));
#pragma unroll
            for (int mt = 0; mt < 4; mt++)
#pragma unroll
                for (int nt = 0; nt < 4; nt++)
                    mma_f16(acc[mt][nt][0], acc[mt][nt][1],
                            acc[mt][nt][2], acc[mt][nt][3],
                            afr[mt][0], afr[mt][1], afr[mt][2], afr[mt][3],
                            bfr[nt][2 * ks], bfr[nt][2 * ks + 1]);
        }
        __syncthreads();
    }

#pragma unroll
    for (int mt = 0; mt < 4; mt++) {
        const int r0 = by + wm + mt * 16 + (lane >> 2);
#pragma unroll
        for (int nt = 0; nt < 4; nt++) {
            const int col = bx + wn + nt * 8 + 2 * (lane & 3);
            if (HOUT) {
                __half* C = (__half*)Cv;
                *(__half2*)(C + (size_t)r0 * N + col) =
                    __floats2half2_rn(acc[mt][nt][0], acc[mt][nt][1]);
                *(__half2*)(C + (size_t)(r0 + 8) * N + col) =
                    __floats2half2_rn(acc[mt][nt][2], acc[mt][nt][3]);
            } else {
                float* C = (float*)Cv;
                const float bv0 = bias ? bias[col] : 0.f;
                const float bv1 = bias ? bias[col + 1] : 0.f;
                float2 v0 = { acc[mt][nt][0] + bv0, acc[mt][nt][1] + bv1 };
                float2 v1 = { acc[mt][nt][2] + bv0, acc[mt][nt][3] + bv1 };
                *(float2*)(C + (size_t)r0 * N + col) = v0;
                *(float2*)(C + (size_t)(r0 + 8) * N + col) = v1;
            }
        }
    }
}

// ---------------------------------------------------------------------------
// fp16 flash attention. grid=(SEQ_N/256, NHEAD, B), 256 thr, warp m-tile 32.
// Q staged once; K/V cp.async double-buffered 64-key tiles (row-natural);
// fragments via ldmatrix (K: plain, V: .trans); P stays in registers.
// Output written fp16.
// ---------------------------------------------------------------------------
#define QSH 72
#define ATTN_SMEM ((256 * QSH + 2 * 64 * QSH + 2 * 64 * QSH) * 2)

__global__ __launch_bounds__(256) void attn_tc(
    const __half* __restrict__ Qg, const __half* __restrict__ Kg,
    const __half* __restrict__ Vg, __half* __restrict__ Og)
{
    extern __shared__ __half sm[];
    __half* Qs = sm;                       // [256][QSH]
    __half* Ksb[2] = { Qs + 256 * QSH, Qs + 256 * QSH + 64 * QSH };
    __half* Vsb[2] = { Qs + 256 * QSH + 2 * 64 * QSH,
                       Qs + 256 * QSH + 3 * 64 * QSH };

    const int tid    = threadIdx.x;
    const int lane   = tid & 31;
    const int wid    = tid >> 5;
    const int qbase  = blockIdx.z * SEQ_N + blockIdx.x * 256;
    const int kvbase = blockIdx.z * SEQ_M;
    const int hcol   = blockIdx.y * HDIM;

    auto issueKV = [&](int st, int kt) {
#pragma unroll
        for (int i = 0; i < 2; i++) {
            const int idx = tid + 256 * i;
            const int r = idx >> 3, c = idx & 7;
            cp16(s2u(Ksb[st] + r * QSH + c * 8),
                 Kg + (size_t)(kvbase + kt + r) * EMB + hcol + c * 8);
        }
#pragma unroll
        for (int i = 0; i < 2; i++) {
            const int idx = tid + 256 * i;
            const int r = idx >> 3, c = idx & 7;
            cp16(s2u(Vsb[st] + r * QSH + c * 8),
                 Vg + (size_t)(kvbase + kt + r) * EMB + hcol + c * 8);
        }
        cp_commit();
    };

    // Stage Q (256x64) + first K/V tile
#pragma unroll
    for (int i = 0; i < 8; i++) {
        const int idx = tid + 256 * i;
        const int r = idx >> 3, c = idx & 7;
        cp16(s2u(Qs + r * QSH + c * 8),
             Qg + (size_t)(qbase + r) * EMB + hcol + c * 8);
    }
    issueKV(0, 0);

    float mrun[2][2], lrun[2][2], oacc[2][8][4];
#pragma unroll
    for (int mt = 0; mt < 2; mt++) {
        mrun[mt][0] = -1e30f; mrun[mt][1] = -1e30f;
        lrun[mt][0] = 0.f;    lrun[mt][1] = 0.f;
#pragma unroll
        for (int nt = 0; nt < 8; nt++)
#pragma unroll
            for (int c = 0; c < 4; c++) oacc[mt][nt][c] = 0.f;
    }

    const int NT = SEQ_M / 64;
    for (int it = 0; it < NT; it++) {
        const int st = it & 1;
        if (it + 1 < NT) { issueKV(st ^ 1, (it + 1) * 64); cp_wait<1>(); }
        else             { cp_wait<0>(); }
        __syncthreads();

        const __half* ks_ = Ksb[st];
        const __half* vs_ = Vsb[st];

        // S = Q @ K^T
        float sacc[2][8][4];
#pragma unroll
        for (int mt = 0; mt < 2; mt++)
#pragma unroll
            for (int nt = 0; nt < 8; nt++)
#pragma unroll
                for (int c = 0; c < 4; c++) sacc[mt][nt][c] = 0.f;

#pragma unroll
        for (int g = 0; g < 2; g++) {
            unsigned kfr[8][4];
#pragma unroll
            for (int nt = 0; nt < 8; nt++)
                ldsm4(kfr[nt], s2u(ks_ + (nt * 8 + (lane & 7)) * QSH
                                       + g * 32 + ((lane >> 3) & 3) * 8));
#pragma unroll
            for (int h = 0; h < 2; h++) {
                const int ks = 2 * g + h;
                unsigned aq[2][4];
#pragma unroll
                for (int mt = 0; mt < 2; mt++)
                    ldsm4(aq[mt], s2u(Qs + (wid * 32 + mt * 16 + (lane & 15)) * QSH
                                         + ks * 16 + ((lane >> 4) << 3)));
#pragma unroll
                for (int nt = 0; nt < 8; nt++)
#pragma unroll
                    for (int mt = 0; mt < 2; mt++)
                        mma_f16(sacc[mt][nt][0], sacc[mt][nt][1],
                                sacc[mt][nt][2], sacc[mt][nt][3],
                                aq[mt][0], aq[mt][1], aq[mt][2], aq[mt][3],
                                kfr[nt][2 * h], kfr[nt][2 * h + 1]);
            }
        }

        // Online softmax (exp2 domain)
        float vm[2][2] = { {-1e30f, -1e30f}, {-1e30f, -1e30f} };
#pragma unroll
        for (int mt = 0; mt < 2; mt++)
#pragma unroll
            for (int nt = 0; nt < 8; nt++) {
#pragma unroll
                for (int c = 0; c < 4; c++) sacc[mt][nt][c] *= SCALE_L2E;
                vm[mt][0] = fmaxf(vm[mt][0], fmaxf(sacc[mt][nt][0], sacc[mt][nt][1]));
                vm[mt][1] = fmaxf(vm[mt][1], fmaxf(sacc[mt][nt][2], sacc[mt][nt][3]));
            }
#pragma unroll
        for (int mt = 0; mt < 2; mt++)
#pragma unroll
            for (int h = 0; h < 2; h++) {
                float v = vm[mt][h];
                v = fmaxf(v, __shfl_xor_sync(0xffffffffu, v, 1));
                v = fmaxf(v, __shfl_xor_sync(0xffffffffu, v, 2));
                vm[mt][h] = v;
            }

        float corr[2][2], rs[2][2];
#pragma unroll
        for (int mt = 0; mt < 2; mt++)
#pragma unroll
            for (int h = 0; h < 2; h++) {
                const float mn = fmaxf(mrun[mt][h], vm[mt][h]);
                corr[mt][h] = ex2f(mrun[mt][h] - mn);
                mrun[mt][h] = mn;
                rs[mt][h] = 0.f;
            }
#pragma unroll
        for (int mt = 0; mt < 2; mt++)
#pragma unroll
            for (int nt = 0; nt < 8; nt++) {
                sacc[mt][nt][0] = ex2f(sacc[mt][nt][0] - mrun[mt][0]);
                sacc[mt][nt][1] = ex2f(sacc[mt][nt][1] - mrun[mt][0]);
                sacc[mt][nt][2] = ex2f(sacc[mt][nt][2] - mrun[mt][1]);
                sacc[mt][nt][3] = ex2f(sacc[mt][nt][3] - mrun[mt][1]);
                rs[mt][0] += sacc[mt][nt][0] + sacc[mt][nt][1];
                rs[mt][1] += sacc[mt][nt][2] + sacc[mt][nt][3];
            }
#pragma unroll
        for (int mt = 0; mt < 2; mt++)
#pragma unroll
            for (int h = 0; h < 2; h++) {
                float r = rs[mt][h];
                r += __shfl_xor_sync(0xffffffffu, r, 1);
                r += __shfl_xor_sync(0xffffffffu, r, 2);
                lrun[mt][h] = lrun[mt][h] * corr[mt][h] + r;
            }
#pragma unroll
        for (int mt = 0; mt < 2; mt++)
#pragma unroll
            for (int nt = 0; nt < 8; nt++) {
                oacc[mt][nt][0] *= corr[mt][0]; oacc[mt][nt][1] *= corr[mt][0];
                oacc[mt][nt][2] *= corr[mt][1]; oacc[mt][nt][3] *= corr[mt][1];
            }

        // O += P @ V (V via ldmatrix.trans, P from sacc registers)
#pragma unroll
        for (int g = 0; g < 2; g++) {
            unsigned vfr[8][4];
#pragma unroll
            for (int nt = 0; nt < 8; nt++)
                ldsm4t(vfr[nt], s2u(vs_ + (g * 32 + lane) * QSH + nt * 8));
#pragma unroll
            for (int h = 0; h < 2; h++) {
                const int ksi = 2 * g + h;
                unsigned pa[2][4];
#pragma unroll
                for (int mt = 0; mt < 2; mt++) {
                    pa[mt][0] = packh2(sacc[mt][2 * ksi][0],     sacc[mt][2 * ksi][1]);
                    pa[mt][1] = packh2(sacc[mt][2 * ksi][2],     sacc[mt][2 * ksi][3]);
                    pa[mt][2] = packh2(sacc[mt][2 * ksi + 1][0], sacc[mt][2 * ksi + 1][1]);
                    pa[mt][3] = packh2(sacc[mt][2 * ksi + 1][2], sacc[mt][2 * ksi + 1][3]);
                }
#pragma unroll
                for (int nt = 0; nt < 8; nt++)
#pragma unroll
                    for (int mt = 0; mt < 2; mt++)
                        mma_f16(oacc[mt][nt][0], oacc[mt][nt][1],
                                oacc[mt][nt][2], oacc[mt][nt][3],
                                pa[mt][0], pa[mt][1], pa[mt][2], pa[mt][3],
                                vfr[nt][2 * h], vfr[nt][2 * h + 1]);
            }
        }
        __syncthreads();
    }

    // Epilogue (fp16 out)
#pragma unroll
    for (int mt = 0; mt < 2; mt++) {
        const float inv0 = 1.f / lrun[mt][0];
        const float inv1 = 1.f / lrun[mt][1];
        const int r0 = qbase + wid * 32 + mt * 16 + (lane >> 2);
#pragma unroll
        for (int nt = 0; nt < 8; nt++) {
            const int col = hcol + nt * 8 + 2 * (lane & 3);
            *(__half2*)(Og + (size_t)r0 * EMB + col) =
                __floats2half2_rn(oacc[mt][nt][0] * inv0, oacc[mt][nt][1] * inv0);
            *(__half2*)(Og + (size_t)(r0 + 8) * EMB + col) =
                __floats2half2_rn(oacc[mt][nt][2] * inv1, oacc[mt][nt][3] * inv1);
        }
    }
}

// ---------------------------------------------------------------------------
extern "C" void kernel_launch(void* const* d_in, const int* in_sizes, int n_in,
                              void* d_out, int out_size)
{
    const float* tokens  = (const float*)d_in[0];
    const float* context = (const float*)d_in[1];
    const float* Wq      = (const float*)d_in[2];
    const float* Wk      = (const float*)d_in[3];
    const float* Wv      = (const float*)d_in[4];
    const float* Wo      = (const float*)d_in[5];
    const float* bo      = (const float*)d_in[6];
    float* out = (float*)d_out;

    __half *ht, *hc, *hwq, *hwk, *hwv, *hwo, *hQ, *hK, *hV, *hA;
    cudaGetSymbolAddress((void**)&ht,  g_ht);
    cudaGetSymbolAddress((void**)&hc,  g_hc);
    cudaGetSymbolAddress((void**)&hwq, g_hwq);
    cudaGetSymbolAddress((void**)&hwk, g_hwk);
    cudaGetSymbolAddress((void**)&hwv, g_hwv);
    cudaGetSymbolAddress((void**)&hwo, g_hwo);
    cudaGetSymbolAddress((void**)&hQ,  g_hQ);
    cudaGetSymbolAddress((void**)&hK,  g_hK);
    cudaGetSymbolAddress((void**)&hV,  g_hV);
    cudaGetSymbolAddress((void**)&hA,  g_hA);

    cudaFuncSetAttribute(attn_tc,
                         cudaFuncAttributeMaxDynamicSharedMemorySize, ATTN_SMEM);

    // Convert inputs/weights to fp16 (once per launch)
    auto cvt = [&](const float* s, __half* d, int n) {
        const int n4 = n / 4;
        f2h<<<(n4 + 255) / 256, 256>>>((const float4*)s, (uint2*)d, n4);
    };
    cvt(tokens,  ht,  TOKENS_M * EMB);
    cvt(context, hc,  CTX_M * CTXD);
    cvt(Wq,  hwq, EMB * EMB);
    cvt(Wk,  hwk, CTXD * EMB);
    cvt(Wv,  hwv, CTXD * EMB);
    cvt(Wo,  hwo, EMB * EMB);

    // Projections (fp16 in, fp16 out)
    gemm_h<true><<<dim3(EMB / 128, TOKENS_M / 128), 256>>>(
        ht, hwq, hQ, TOKENS_M, EMB, EMB, nullptr);
    gemm_h<true><<<dim3(EMB / 128, CTX_M / 128), 256>>>(
        hc, hwk, hK, CTX_M, EMB, CTXD, nullptr);
    gemm_h<true><<<dim3(EMB / 128, CTX_M / 128), 256>>>(
        hc, hwv, hV, CTX_M, EMB, CTXD, nullptr);

    // Fused attention (fp16 in/out)
    attn_tc<<<dim3(SEQ_N / 256, NHEAD, 4), 256, ATTN_SMEM>>>(hQ, hK, hV, hA);

    // Output projection + bias (fp16 in, fp32 out)
    gemm_h<false><<<dim3(EMB / 128, TOKENS_M / 128), 256>>>(
        hA, hwo, out, TOKENS_M, EMB, EMB, bo);
}